// round 2
// baseline (speedup 1.0000x reference)
#include <cuda_runtime.h>

#define NN 50000
#define NE 800000
#define HID 256
#define OC  40

// ---------------- scratch (static device allocations; no cudaMalloc allowed) ----
__device__ float g_deg[NN];
__device__ float g_dinv[NN];
__device__ float g_norm[NE];
__device__ float g_bufA[NN * HID];
__device__ float g_bufB[NN * HID];
__device__ float g_t40[NN * OC];
__device__ float g_y0[NN * OC];
__device__ float g_y1[NN * OC];
__device__ float g_bnsum[HID];
__device__ float g_bnsq[HID];
__device__ float g_scale[HID];
__device__ float g_shift[HID];

// ---------------- small utility kernels ----------------------------------------
__global__ void k_fill(float* p, float v, int n) {
    int i = blockIdx.x * blockDim.x + threadIdx.x;
    if (i < n) p[i] = v;
}

__global__ void k_deg(const int* __restrict__ row, const float* __restrict__ w) {
    int e = blockIdx.x * blockDim.x + threadIdx.x;
    if (e < NE) atomicAdd(&g_deg[row[e]], w[e]);
}

__global__ void k_dinv() {
    int i = blockIdx.x * blockDim.x + threadIdx.x;
    if (i < NN) {
        float d = g_deg[i];
        g_dinv[i] = (d > 0.f) ? rsqrtf(fmaxf(d, 1e-12f)) : 0.f;
    }
}

__global__ void k_norm(const int* __restrict__ row, const int* __restrict__ col,
                       const float* __restrict__ w) {
    int e = blockIdx.x * blockDim.x + threadIdx.x;
    if (e < NE) g_norm[e] = g_dinv[row[e]] * w[e] * g_dinv[col[e]];
}

// ---------------- GEMM: C[M,N] = A[M,K] @ B[K,N], N multiple of 64 --------------
__global__ void k_gemm64(const float* __restrict__ A, const float* __restrict__ B,
                         float* __restrict__ C, int M, int N, int K) {
    __shared__ float As[64][33];
    __shared__ float Bs[32][64];
    int bm = blockIdx.x * 64, bn = blockIdx.y * 64;
    int tx = threadIdx.x & 15, ty = threadIdx.x >> 4;
    float acc[4][4] = {};
    for (int k0 = 0; k0 < K; k0 += 32) {
        int r  = threadIdx.x >> 2;
        int kk = (threadIdx.x & 3) * 8;
        int gr = bm + r;
        #pragma unroll
        for (int i = 0; i < 8; i++)
            As[r][kk + i] = (gr < M) ? A[(long long)gr * K + k0 + kk + i] : 0.f;
        int kB = threadIdx.x >> 3;
        int nn = (threadIdx.x & 7) * 8;
        #pragma unroll
        for (int i = 0; i < 8; i++)
            Bs[kB][nn + i] = B[(k0 + kB) * N + bn + nn + i];
        __syncthreads();
        #pragma unroll
        for (int k = 0; k < 32; k++) {
            float a[4], b[4];
            #pragma unroll
            for (int i = 0; i < 4; i++) a[i] = As[ty * 4 + i][k];
            #pragma unroll
            for (int j = 0; j < 4; j++) b[j] = Bs[k][tx * 4 + j];
            #pragma unroll
            for (int i = 0; i < 4; i++)
                #pragma unroll
                for (int j = 0; j < 4; j++)
                    acc[i][j] += a[i] * b[j];
        }
        __syncthreads();
    }
    #pragma unroll
    for (int i = 0; i < 4; i++) {
        int gr = bm + ty * 4 + i;
        if (gr < M)
            #pragma unroll
            for (int j = 0; j < 4; j++)
                C[(long long)gr * N + bn + tx * 4 + j] = acc[i][j];
    }
}

// ---------------- GEMM: C[M,40] = A[M,K] @ B[K,40] ------------------------------
__global__ void k_gemm40(const float* __restrict__ A, const float* __restrict__ B,
                         float* __restrict__ C, int M, int K) {
    __shared__ float As[64][33];
    __shared__ float Bs[32][40];
    int bm = blockIdx.x * 64;
    int r  = threadIdx.x >> 2;   // 0..63
    int cg = threadIdx.x & 3;    // 0..3
    float acc[10] = {};
    for (int k0 = 0; k0 < K; k0 += 32) {
        int kk = (threadIdx.x & 3) * 8;
        int gr = bm + r;
        #pragma unroll
        for (int i = 0; i < 8; i++)
            As[r][kk + i] = (gr < M) ? A[(long long)gr * K + k0 + kk + i] : 0.f;
        for (int i = threadIdx.x; i < 32 * 40; i += 256) {
            int k = i / 40, n = i % 40;
            Bs[k][n] = B[(k0 + k) * 40 + n];
        }
        __syncthreads();
        #pragma unroll
        for (int k = 0; k < 32; k++) {
            float a = As[r][k];
            #pragma unroll
            for (int j = 0; j < 10; j++) acc[j] += a * Bs[k][cg + j * 4];
        }
        __syncthreads();
    }
    int gr = bm + r;
    if (gr < M)
        #pragma unroll
        for (int j = 0; j < 10; j++) C[gr * 40 + cg + j * 4] = acc[j];
}

// ---------------- SpMM pieces ----------------------------------------------------
// init: out = dinv[i]^2 * in + bias (self-loop term + bias), fully overwrites out
__global__ void k_init256(const float* __restrict__ in, float* __restrict__ out,
                          const float* __restrict__ bias) {
    int idx = blockIdx.x * blockDim.x + threadIdx.x;
    if (idx < NN * HID) {
        int i = idx >> 8, c = idx & 255;
        float d = g_dinv[i];
        out[idx] = d * d * in[idx] + bias[c];
    }
}

__global__ void k_init40(const float* __restrict__ in, float* __restrict__ out,
                         const float* __restrict__ bias) {
    int idx = blockIdx.x * blockDim.x + threadIdx.x;
    if (idx < NN * OC) {
        int i = idx / OC, c = idx % OC;
        float d = g_dinv[i];
        float b = bias ? bias[c] : 0.f;
        out[idx] = d * d * in[idx] + b;
    }
}

// edge scatter: out[row] += norm_e * in[col], 256 channels as float4 quads
__global__ void k_spmm256(const int* __restrict__ row, const int* __restrict__ col,
                          const float* __restrict__ in, float* __restrict__ out) {
    int idx = blockIdx.x * blockDim.x + threadIdx.x;
    if (idx >= NE * 64) return;
    int e = idx >> 6, q = idx & 63;
    float nw = g_norm[e];
    const float4* in4 = (const float4*)in;
    float4 v = in4[col[e] * 64 + q];
    int base = row[e] * 256 + q * 4;
    atomicAdd(&out[base + 0], nw * v.x);
    atomicAdd(&out[base + 1], nw * v.y);
    atomicAdd(&out[base + 2], nw * v.z);
    atomicAdd(&out[base + 3], nw * v.w);
}

// edge scatter: 40 channels = 10 float4 quads per edge
__global__ void k_spmm40(const int* __restrict__ row, const int* __restrict__ col,
                         const float* __restrict__ in, float* __restrict__ out) {
    int idx = blockIdx.x * blockDim.x + threadIdx.x;
    if (idx >= NE * 10) return;
    int e = idx / 10, q = idx % 10;
    float nw = g_norm[e];
    const float4* in4 = (const float4*)in;
    float4 v = in4[col[e] * 10 + q];
    int base = row[e] * 40 + q * 4;
    atomicAdd(&out[base + 0], nw * v.x);
    atomicAdd(&out[base + 1], nw * v.y);
    atomicAdd(&out[base + 2], nw * v.z);
    atomicAdd(&out[base + 3], nw * v.w);
}

// ---------------- BatchNorm -------------------------------------------------------
__global__ void k_bnzero() {
    int c = threadIdx.x;
    g_bnsum[c] = 0.f;
    g_bnsq[c]  = 0.f;
}

__global__ void k_bnstats(const float* __restrict__ h) {
    int c = threadIdx.x;
    float s = 0.f, s2 = 0.f;
    for (int r = blockIdx.x; r < NN; r += gridDim.x) {
        float v = h[r * HID + c];
        s += v;
        s2 += v * v;
    }
    atomicAdd(&g_bnsum[c], s);
    atomicAdd(&g_bnsq[c], s2);
}

__global__ void k_bnfin(const float* __restrict__ gamma, const float* __restrict__ beta) {
    int c = threadIdx.x;
    float mu  = g_bnsum[c] * (1.f / NN);
    float var = g_bnsq[c] * (1.f / NN) - mu * mu;
    float sc  = gamma[c] * rsqrtf(var + 1e-5f);
    g_scale[c] = sc;
    g_shift[c] = beta[c] - mu * sc;
}

__global__ void k_bnapply(const float* __restrict__ in, float* __restrict__ out) {
    int idx = blockIdx.x * blockDim.x + threadIdx.x;
    if (idx < NN * HID) {
        int c = idx & 255;
        out[idx] = fmaxf(in[idx] * g_scale[c] + g_shift[c], 0.f);
    }
}

// ---------------- host orchestration ----------------------------------------------
extern "C" void kernel_launch(void* const* d_in, const int* in_sizes, int n_in,
                              void* d_out, int out_size) {
    const float* x    = (const float*)d_in[0];
    const int*   ei   = (const int*)d_in[1];
    const int*   row  = ei;
    const int*   col  = ei + NE;
    const float* lab0 = (const float*)d_in[2];
    const float* lab1 = (const float*)d_in[3];
    const float* ew   = (const float*)d_in[4];
    const float* W0   = (const float*)d_in[5];
    const float* b0   = (const float*)d_in[6];
    const float* W1   = (const float*)d_in[7];
    const float* b1   = (const float*)d_in[8];
    const float* W2   = (const float*)d_in[9];
    const float* b2   = (const float*)d_in[10];
    const float* g0   = (const float*)d_in[11];
    const float* be0  = (const float*)d_in[12];
    const float* g1   = (const float*)d_in[13];
    const float* be1  = (const float*)d_in[14];
    float* out = (float*)d_out;

    float *bufA, *bufB, *t40, *y0, *y1, *degp;
    cudaGetSymbolAddress((void**)&bufA, g_bufA);
    cudaGetSymbolAddress((void**)&bufB, g_bufB);
    cudaGetSymbolAddress((void**)&t40,  g_t40);
    cudaGetSymbolAddress((void**)&y0,   g_y0);
    cudaGetSymbolAddress((void**)&y1,   g_y1);
    cudaGetSymbolAddress((void**)&degp, g_deg);

    const int T = 256;
    const int gN    = (NN + T - 1) / T;
    const int gE    = (NE + T - 1) / T;
    const int gNH   = (NN * HID + T - 1) / T;
    const int gN40  = (NN * OC + T - 1) / T;
    const int gE64  = (NE * 64 + T - 1) / T;
    const int gE10  = (NE * 10 + T - 1) / T;
    const int gM64  = (NN + 63) / 64;

    // normalization: deg (self-loop baked in as init=1), dinv, per-edge norm
    k_fill<<<gN, T>>>(degp, 1.0f, NN);
    k_deg<<<gE, T>>>(row, ew);
    k_dinv<<<gN, T>>>();
    k_norm<<<gE, T>>>(row, col, ew);

    // ---- layer 0: prop(x @ W0) + b0 -> BN -> ReLU
    dim3 g0grid(gM64, HID / 64);
    k_gemm64<<<g0grid, T>>>(x, W0, bufA, NN, HID, 512);
    k_init256<<<gNH, T>>>(bufA, bufB, b0);
    k_spmm256<<<gE64, T>>>(row, col, bufA, bufB);
    k_bnzero<<<1, HID>>>();
    k_bnstats<<<256, HID>>>(bufB);
    k_bnfin<<<1, HID>>>(g0, be0);
    k_bnapply<<<gNH, T>>>(bufB, bufA);

    // ---- layer 1: prop(h @ W1) + b1 -> BN -> ReLU
    k_gemm64<<<g0grid, T>>>(bufA, W1, bufB, NN, HID, HID);
    k_init256<<<gNH, T>>>(bufB, bufA, b1);
    k_spmm256<<<gE64, T>>>(row, col, bufB, bufA);
    k_bnzero<<<1, HID>>>();
    k_bnstats<<<256, HID>>>(bufA);
    k_bnfin<<<1, HID>>>(g1, be1);
    k_bnapply<<<gNH, T>>>(bufA, bufB);

    // ---- layer 2: out = prop(h @ W2) + b2  (written straight into d_out)
    k_gemm40<<<gM64, T>>>(bufB, W2, t40, NN, HID);
    k_init40<<<gN40, T>>>(t40, out, b2);
    k_spmm40<<<gE10, T>>>(row, col, t40, out);

    // ---- label propagation: 3 iterations each on both label matrices
    float* dst1 = out + NN * OC;
    k_init40<<<gN40, T>>>(lab0, y0, nullptr);
    k_spmm40<<<gE10, T>>>(row, col, lab0, y0);
    k_init40<<<gN40, T>>>(y0, y1, nullptr);
    k_spmm40<<<gE10, T>>>(row, col, y0, y1);
    k_init40<<<gN40, T>>>(y1, dst1, nullptr);
    k_spmm40<<<gE10, T>>>(row, col, y1, dst1);

    float* dst2 = out + 2 * NN * OC;
    k_init40<<<gN40, T>>>(lab1, y0, nullptr);
    k_spmm40<<<gE10, T>>>(row, col, lab1, y0);
    k_init40<<<gN40, T>>>(y0, y1, nullptr);
    k_spmm40<<<gE10, T>>>(row, col, y0, y1);
    k_init40<<<gN40, T>>>(y1, dst2, nullptr);
    k_spmm40<<<gE10, T>>>(row, col, y1, dst2);
}

// round 4
// speedup vs baseline: 1.6338x; 1.6338x over previous
#include <cuda_runtime.h>

#define NN 50000
#define NE 800000
#define HID 256
#define OC  40

// ---------------- scratch (static device allocations) ---------------------------
__device__ float g_deg[NN];
__device__ float g_dinv[NN];
__device__ int   g_cnt[NN];
__device__ int   g_off[NN + 1];
__device__ int   g_cur[NN];
__device__ int   g_ccol[NE];
__device__ float g_cw[NE];
__device__ float g_bufA[NN * HID];
__device__ float g_bufB[NN * HID];
__device__ float g_t40[NN * OC];
__device__ float g_y0[NN * OC];
__device__ float g_y1[NN * OC];
__device__ float g_bnsum[HID];
__device__ float g_bnsq[HID];
__device__ float g_scale[HID];
__device__ float g_shift[HID];

// ---------------- normalization + CSR build --------------------------------------
__global__ void k_fill(float* p, float v, int n) {
    int i = blockIdx.x * blockDim.x + threadIdx.x;
    if (i < n) p[i] = v;
}
__global__ void k_izero(int* p, int n) {
    int i = blockIdx.x * blockDim.x + threadIdx.x;
    if (i < n) p[i] = 0;
}

__global__ void k_deg(const int* __restrict__ row, const float* __restrict__ w) {
    int e = blockIdx.x * blockDim.x + threadIdx.x;
    if (e < NE) atomicAdd(&g_deg[row[e]], w[e]);
}

__global__ void k_dinv() {
    int i = blockIdx.x * blockDim.x + threadIdx.x;
    if (i < NN) {
        float d = g_deg[i];
        g_dinv[i] = (d > 0.f) ? rsqrtf(fmaxf(d, 1e-12f)) : 0.f;
    }
}

__global__ void k_count(const int* __restrict__ row) {
    int e = blockIdx.x * blockDim.x + threadIdx.x;
    if (e < NE) atomicAdd(&g_cnt[row[e]], 1);
}

// single-block exclusive scan over g_cnt -> g_off (and g_cur copy)
__global__ void k_scan() {
    __shared__ int s[1024];
    __shared__ int carry;
    int tid = threadIdx.x;
    if (tid == 0) carry = 0;
    __syncthreads();
    for (int base = 0; base < NN; base += 1024) {
        int i = base + tid;
        int v = (i < NN) ? g_cnt[i] : 0;
        s[tid] = v;
        __syncthreads();
        #pragma unroll
        for (int o = 1; o < 1024; o <<= 1) {
            int t = (tid >= o) ? s[tid - o] : 0;
            __syncthreads();
            s[tid] += t;
            __syncthreads();
        }
        if (i < NN) {
            int excl = carry + s[tid] - v;
            g_off[i] = excl;
            g_cur[i] = excl;
        }
        __syncthreads();
        if (tid == 0) carry += s[1023];
        __syncthreads();
    }
    if (tid == 0) g_off[NN] = carry;
}

// scatter edges into CSR slots; weight = dinv[r]*w*dinv[c]
__global__ void k_scatter(const int* __restrict__ row, const int* __restrict__ col,
                          const float* __restrict__ w) {
    int e = blockIdx.x * blockDim.x + threadIdx.x;
    if (e < NE) {
        int r = row[e], c = col[e];
        int p = atomicAdd(&g_cur[r], 1);
        g_ccol[p] = c;
        g_cw[p] = g_dinv[r] * w[e] * g_dinv[c];
    }
}

// ---------------- GEMM: C[M,N] = A[M,K] @ B[K,N]; 128x64 tile, 8x4 micro --------
__global__ void __launch_bounds__(256) k_gemm128(const float* __restrict__ A,
                                                 const float* __restrict__ B,
                                                 float* __restrict__ C,
                                                 int M, int N, int K) {
    __shared__ float As[16][132];
    __shared__ float Bs[16][64];
    int bm = blockIdx.x * 128, bn = blockIdx.y * 64;
    int tx = threadIdx.x & 15;   // n: 16 * 4
    int ty = threadIdx.x >> 4;   // m: 16 * 8
    float acc[8][4] = {};
    for (int k0 = 0; k0 < K; k0 += 16) {
        // load A tile 128x16: thread -> m = tid>>1, 8 consecutive k
        {
            int m  = threadIdx.x >> 1;
            int ks = (threadIdx.x & 1) * 8;
            int gr = bm + m;
            #pragma unroll
            for (int i = 0; i < 8; i++)
                As[ks + i][m] = (gr < M) ? A[(long long)gr * K + k0 + ks + i] : 0.f;
        }
        // load B tile 16x64: thread -> k = tid>>4, 4 consecutive n (float4)
        {
            int k  = threadIdx.x >> 4;
            int n4 = (threadIdx.x & 15) * 4;
            float4 v = *(const float4*)&B[(long long)(k0 + k) * N + bn + n4];
            Bs[k][n4 + 0] = v.x; Bs[k][n4 + 1] = v.y;
            Bs[k][n4 + 2] = v.z; Bs[k][n4 + 3] = v.w;
        }
        __syncthreads();
        #pragma unroll
        for (int k = 0; k < 16; k++) {
            float a[8], b[4];
            #pragma unroll
            for (int i = 0; i < 8; i++) a[i] = As[k][ty * 8 + i];
            #pragma unroll
            for (int j = 0; j < 4; j++) b[j] = Bs[k][tx * 4 + j];
            #pragma unroll
            for (int i = 0; i < 8; i++)
                #pragma unroll
                for (int j = 0; j < 4; j++)
                    acc[i][j] += a[i] * b[j];
        }
        __syncthreads();
    }
    #pragma unroll
    for (int i = 0; i < 8; i++) {
        int gr = bm + ty * 8 + i;
        if (gr < M) {
            float4 v = make_float4(acc[i][0], acc[i][1], acc[i][2], acc[i][3]);
            *(float4*)&C[(long long)gr * N + bn + tx * 4] = v;
        }
    }
}

// ---------------- GEMM: C[M,40] = A[M,K] @ B[K,40] ------------------------------
__global__ void k_gemm40(const float* __restrict__ A, const float* __restrict__ B,
                         float* __restrict__ C, int M, int K) {
    __shared__ float As[64][33];
    __shared__ float Bs[32][40];
    int bm = blockIdx.x * 64;
    int r  = threadIdx.x >> 2;
    int cg = threadIdx.x & 3;
    float acc[10] = {};
    for (int k0 = 0; k0 < K; k0 += 32) {
        int kk = (threadIdx.x & 3) * 8;
        int gr = bm + r;
        #pragma unroll
        for (int i = 0; i < 8; i++)
            As[r][kk + i] = (gr < M) ? A[(long long)gr * K + k0 + kk + i] : 0.f;
        for (int i = threadIdx.x; i < 32 * 40; i += 256) {
            int k = i / 40, n = i % 40;
            Bs[k][n] = B[(k0 + k) * 40 + n];
        }
        __syncthreads();
        #pragma unroll
        for (int k = 0; k < 32; k++) {
            float a = As[r][k];
            #pragma unroll
            for (int j = 0; j < 10; j++) acc[j] += a * Bs[k][cg + j * 4];
        }
        __syncthreads();
    }
    int gr = bm + r;
    if (gr < M)
        #pragma unroll
        for (int j = 0; j < 10; j++) C[gr * 40 + cg + j * 4] = acc[j];
}

// ---------------- gather SpMM: out[r] = d^2*in[r] + bias + sum_e w*in[col] -------
__global__ void __launch_bounds__(256) k_gspmm256(const float* __restrict__ in,
                                                  float* __restrict__ out,
                                                  const float* __restrict__ bias) {
    __shared__ int   scol[256];
    __shared__ float sw[256];
    int r = blockIdx.x;
    int ch = threadIdx.x;
    int beg = g_off[r], end = g_off[r + 1];
    float d = g_dinv[r];
    float acc = d * d * in[r * HID + ch] + bias[ch];
    for (int j0 = beg; j0 < end; j0 += 256) {
        int m = min(256, end - j0);
        if (ch < m) { scol[ch] = g_ccol[j0 + ch]; sw[ch] = g_cw[j0 + ch]; }
        __syncthreads();
        #pragma unroll 4
        for (int j = 0; j < m; j++)
            acc += sw[j] * in[scol[j] * HID + ch];
        __syncthreads();
    }
    out[r * HID + ch] = acc;
}

// warp per row, lanes cover 40 channels (lane, and lane+32 for lane<8)
__global__ void __launch_bounds__(256) k_gspmm40(const float* __restrict__ in,
                                                 float* __restrict__ out,
                                                 const float* __restrict__ bias) {
    int r = blockIdx.x * 8 + (threadIdx.x >> 5);
    if (r >= NN) return;
    int lane = threadIdx.x & 31;
    int beg = g_off[r], end = g_off[r + 1];
    float d = g_dinv[r];
    float dd = d * d;
    float acc0 = dd * in[r * OC + lane];
    float acc1 = (lane < 8) ? dd * in[r * OC + 32 + lane] : 0.f;
    #pragma unroll 4
    for (int j = beg; j < end; j++) {
        int c = g_ccol[j];
        float w = g_cw[j];
        acc0 += w * in[c * OC + lane];
        if (lane < 8) acc1 += w * in[c * OC + 32 + lane];
    }
    if (bias) {
        acc0 += bias[lane];
        if (lane < 8) acc1 += bias[32 + lane];
    }
    out[r * OC + lane] = acc0;
    if (lane < 8) out[r * OC + 32 + lane] = acc1;
}

// ---------------- BatchNorm -------------------------------------------------------
__global__ void k_bnzero() {
    int c = threadIdx.x;
    g_bnsum[c] = 0.f;
    g_bnsq[c]  = 0.f;
}

__global__ void k_bnstats(const float* __restrict__ h) {
    int c = threadIdx.x;
    float s = 0.f, s2 = 0.f;
    for (int r = blockIdx.x; r < NN; r += gridDim.x) {
        float v = h[r * HID + c];
        s += v;
        s2 += v * v;
    }
    atomicAdd(&g_bnsum[c], s);
    atomicAdd(&g_bnsq[c], s2);
}

__global__ void k_bnfin(const float* __restrict__ gamma, const float* __restrict__ beta) {
    int c = threadIdx.x;
    float mu  = g_bnsum[c] * (1.f / NN);
    float var = g_bnsq[c] * (1.f / NN) - mu * mu;
    float sc  = gamma[c] * rsqrtf(var + 1e-5f);
    g_scale[c] = sc;
    g_shift[c] = beta[c] - mu * sc;
}

__global__ void k_bnapply(const float* __restrict__ in, float* __restrict__ out) {
    int idx = blockIdx.x * blockDim.x + threadIdx.x;
    if (idx < NN * HID) {
        int c = idx & 255;
        out[idx] = fmaxf(in[idx] * g_scale[c] + g_shift[c], 0.f);
    }
}

// ---------------- host orchestration ----------------------------------------------
extern "C" void kernel_launch(void* const* d_in, const int* in_sizes, int n_in,
                              void* d_out, int out_size) {
    const float* x    = (const float*)d_in[0];
    const int*   ei   = (const int*)d_in[1];
    const int*   row  = ei;
    const int*   col  = ei + NE;
    const float* lab0 = (const float*)d_in[2];
    const float* lab1 = (const float*)d_in[3];
    const float* ew   = (const float*)d_in[4];
    const float* W0   = (const float*)d_in[5];
    const float* b0   = (const float*)d_in[6];
    const float* W1   = (const float*)d_in[7];
    const float* b1   = (const float*)d_in[8];
    const float* W2   = (const float*)d_in[9];
    const float* b2   = (const float*)d_in[10];
    const float* g0   = (const float*)d_in[11];
    const float* be0  = (const float*)d_in[12];
    const float* g1   = (const float*)d_in[13];
    const float* be1  = (const float*)d_in[14];
    float* out = (float*)d_out;

    float *bufA, *bufB, *t40, *y0, *y1, *degp;
    int* cntp;
    cudaGetSymbolAddress((void**)&bufA, g_bufA);
    cudaGetSymbolAddress((void**)&bufB, g_bufB);
    cudaGetSymbolAddress((void**)&t40,  g_t40);
    cudaGetSymbolAddress((void**)&y0,   g_y0);
    cudaGetSymbolAddress((void**)&y1,   g_y1);
    cudaGetSymbolAddress((void**)&degp, g_deg);
    cudaGetSymbolAddress((void**)&cntp, g_cnt);

    const int T = 256;
    const int gN   = (NN + T - 1) / T;
    const int gE   = (NE + T - 1) / T;
    const int gNH  = (NN * HID + T - 1) / T;
    const int gM64 = (NN + 63) / 64;
    const int gRW  = (NN + 7) / 8;   // warp-per-row kernels

    // normalization + CSR build
    k_fill<<<gN, T>>>(degp, 1.0f, NN);
    k_izero<<<gN, T>>>(cntp, NN);
    k_deg<<<gE, T>>>(row, ew);
    k_count<<<gE, T>>>(row);
    k_dinv<<<gN, T>>>();
    k_scan<<<1, 1024>>>();
    k_scatter<<<gE, T>>>(row, col, ew);

    // ---- layer 0
    dim3 gg0((NN + 127) / 128, HID / 64);
    k_gemm128<<<gg0, T>>>(x, W0, bufA, NN, HID, 512);
    k_gspmm256<<<NN, HID>>>(bufA, bufB, b0);
    k_bnzero<<<1, HID>>>();
    k_bnstats<<<256, HID>>>(bufB);
    k_bnfin<<<1, HID>>>(g0, be0);
    k_bnapply<<<gNH, T>>>(bufB, bufA);

    // ---- layer 1
    k_gemm128<<<gg0, T>>>(bufA, W1, bufB, NN, HID, HID);
    k_gspmm256<<<NN, HID>>>(bufB, bufA, b1);
    k_bnzero<<<1, HID>>>();
    k_bnstats<<<256, HID>>>(bufA);
    k_bnfin<<<1, HID>>>(g1, be1);
    k_bnapply<<<gNH, T>>>(bufA, bufB);

    // ---- layer 2 (into d_out)
    k_gemm40<<<gM64, T>>>(bufB, W2, t40, NN, HID);
    k_gspmm40<<<gRW, T>>>(t40, out, b2);

    // ---- label propagation
    float* dst1 = out + NN * OC;
    k_gspmm40<<<gRW, T>>>(lab0, y0, nullptr);
    k_gspmm40<<<gRW, T>>>(y0, y1, nullptr);
    k_gspmm40<<<gRW, T>>>(y1, dst1, nullptr);

    float* dst2 = out + 2 * NN * OC;
    k_gspmm40<<<gRW, T>>>(lab1, y0, nullptr);
    k_gspmm40<<<gRW, T>>>(y0, y1, nullptr);
    k_gspmm40<<<gRW, T>>>(y1, dst2, nullptr);
}

// round 5
// speedup vs baseline: 2.1750x; 1.3312x over previous
#include <cuda_runtime.h>
#include <mma.h>
using namespace nvcuda;

#define NN  50000
#define NNP 50048          // 391 * 128, padded row count for unguarded GEMM stores
#define NE  800000
#define HID 256
#define OC  40

// ---------------- scratch (static device allocations) ---------------------------
__device__ float g_deg[NN];
__device__ float g_dinv[NN];
__device__ int   g_cnt[NN];
__device__ int   g_off[NN + 1];
__device__ int   g_cur[NN];
__device__ int   g_ccol[NE];
__device__ float g_cw[NE];
__device__ float g_bufA[NNP * HID];
__device__ float g_bufB[NNP * HID];
__device__ float g_t40[NN * OC];
__device__ float g_y0[NN * OC];
__device__ float g_y1[NN * OC];
__device__ float g_y2[NN * OC];
__device__ float g_y3[NN * OC];
__device__ float g_bnsum[HID];
__device__ float g_bnsq[HID];
__device__ float g_scale[HID];
__device__ float g_shift[HID];

// ---------------- normalization + CSR build --------------------------------------
__global__ void k_fillinit(float* degp, int* cntp, int n) {
    int i = blockIdx.x * blockDim.x + threadIdx.x;
    if (i < n) { degp[i] = 1.0f; cntp[i] = 0; }
}

__global__ void k_degcnt(const int* __restrict__ row, const float* __restrict__ w) {
    int e = blockIdx.x * blockDim.x + threadIdx.x;
    if (e < NE) {
        int r = row[e];
        atomicAdd(&g_deg[r], w[e]);
        atomicAdd(&g_cnt[r], 1);
    }
}

__global__ void k_dinv() {
    int i = blockIdx.x * blockDim.x + threadIdx.x;
    if (i < NN) {
        float d = g_deg[i];
        g_dinv[i] = (d > 0.f) ? rsqrtf(fmaxf(d, 1e-12f)) : 0.f;
    }
}

// single-block exclusive scan over g_cnt -> g_off (and g_cur copy)
__global__ void k_scan() {
    __shared__ int s[1024];
    __shared__ int carry;
    int tid = threadIdx.x;
    if (tid == 0) carry = 0;
    __syncthreads();
    for (int base = 0; base < NN; base += 1024) {
        int i = base + tid;
        int v = (i < NN) ? g_cnt[i] : 0;
        s[tid] = v;
        __syncthreads();
        #pragma unroll
        for (int o = 1; o < 1024; o <<= 1) {
            int t = (tid >= o) ? s[tid - o] : 0;
            __syncthreads();
            s[tid] += t;
            __syncthreads();
        }
        if (i < NN) {
            int excl = carry + s[tid] - v;
            g_off[i] = excl;
            g_cur[i] = excl;
        }
        __syncthreads();
        if (tid == 0) carry += s[1023];
        __syncthreads();
    }
    if (tid == 0) g_off[NN] = carry;
}

__global__ void k_scatter(const int* __restrict__ row, const int* __restrict__ col,
                          const float* __restrict__ w) {
    int e = blockIdx.x * blockDim.x + threadIdx.x;
    if (e < NE) {
        int r = row[e], c = col[e];
        int p = atomicAdd(&g_cur[r], 1);
        g_ccol[p] = c;
        g_cw[p] = g_dinv[r] * w[e] * g_dinv[c];
    }
}

// ---------------- TF32 tensor-core GEMM: C[M,N] = A[M,K] @ B[K,N] ----------------
// block tile 128x64, 8 warps (4 along m x 2 along n), warp tile 32x32.
// C must be padded (NNP rows) — stores are unguarded. A-loads zero-guarded at M.
__global__ void __launch_bounds__(256) k_gemm_tf32(const float* __restrict__ A,
                                                   const float* __restrict__ B,
                                                   float* __restrict__ C,
                                                   int M, int N, int K) {
    __shared__ float As[128][40];   // [m][k], k chunk 32, pad->40 (160B rows)
    __shared__ float Bs[32][72];    // [k][n], n chunk 64, pad->72 (288B rows)
    int bm = blockIdx.x * 128, bn = blockIdx.y * 64;
    int tid = threadIdx.x;
    int warp = tid >> 5;
    int wm = (warp >> 1) * 32;      // warp m offset in tile
    int wn = (warp & 1) * 32;       // warp n offset in tile

    wmma::fragment<wmma::accumulator, 16, 16, 8, float> c00, c01, c10, c11;
    wmma::fill_fragment(c00, 0.f); wmma::fill_fragment(c01, 0.f);
    wmma::fill_fragment(c10, 0.f); wmma::fill_fragment(c11, 0.f);

    for (int k0 = 0; k0 < K; k0 += 32) {
        // A tile 128x32: thread -> m = tid>>1, 16 consecutive k
        {
            int m  = tid >> 1;
            int ks = (tid & 1) * 16;
            int gr = bm + m;
            if (gr < M) {
                const float4* p = (const float4*)&A[(long long)gr * K + k0 + ks];
                #pragma unroll
                for (int i = 0; i < 4; i++) {
                    float4 v = p[i];
                    As[m][ks + i * 4 + 0] = wmma::__float_to_tf32(v.x);
                    As[m][ks + i * 4 + 1] = wmma::__float_to_tf32(v.y);
                    As[m][ks + i * 4 + 2] = wmma::__float_to_tf32(v.z);
                    As[m][ks + i * 4 + 3] = wmma::__float_to_tf32(v.w);
                }
            } else {
                #pragma unroll
                for (int i = 0; i < 16; i++) As[m][ks + i] = 0.f;
            }
        }
        // B tile 32x64: thread -> k = tid>>3, 8 consecutive n
        {
            int k  = tid >> 3;
            int n8 = (tid & 7) * 8;
            const float4* p = (const float4*)&B[(long long)(k0 + k) * N + bn + n8];
            #pragma unroll
            for (int i = 0; i < 2; i++) {
                float4 v = p[i];
                Bs[k][n8 + i * 4 + 0] = wmma::__float_to_tf32(v.x);
                Bs[k][n8 + i * 4 + 1] = wmma::__float_to_tf32(v.y);
                Bs[k][n8 + i * 4 + 2] = wmma::__float_to_tf32(v.z);
                Bs[k][n8 + i * 4 + 3] = wmma::__float_to_tf32(v.w);
            }
        }
        __syncthreads();
        #pragma unroll
        for (int kk = 0; kk < 32; kk += 8) {
            wmma::fragment<wmma::matrix_a, 16, 16, 8, wmma::precision::tf32, wmma::row_major> a0, a1;
            wmma::fragment<wmma::matrix_b, 16, 16, 8, wmma::precision::tf32, wmma::row_major> b0, b1;
            wmma::load_matrix_sync(a0, &As[wm +  0][kk], 40);
            wmma::load_matrix_sync(a1, &As[wm + 16][kk], 40);
            wmma::load_matrix_sync(b0, &Bs[kk][wn +  0], 72);
            wmma::load_matrix_sync(b1, &Bs[kk][wn + 16], 72);
            wmma::mma_sync(c00, a0, b0, c00);
            wmma::mma_sync(c01, a0, b1, c01);
            wmma::mma_sync(c10, a1, b0, c10);
            wmma::mma_sync(c11, a1, b1, c11);
        }
        __syncthreads();
    }
    float* cp = &C[(long long)(bm + wm) * N + bn + wn];
    wmma::store_matrix_sync(cp,                 c00, N, wmma::mem_row_major);
    wmma::store_matrix_sync(cp + 16,            c01, N, wmma::mem_row_major);
    wmma::store_matrix_sync(cp + 16 * N,        c10, N, wmma::mem_row_major);
    wmma::store_matrix_sync(cp + 16 * N + 16,   c11, N, wmma::mem_row_major);
}

// ---------------- GEMM: C[M,40] = A[M,K] @ B[K,40] (SIMT) ------------------------
__global__ void k_gemm40(const float* __restrict__ A, const float* __restrict__ B,
                         float* __restrict__ C, int M, int K) {
    __shared__ float As[64][33];
    __shared__ float Bs[32][40];
    int bm = blockIdx.x * 64;
    int r  = threadIdx.x >> 2;
    int cg = threadIdx.x & 3;
    float acc[10] = {};
    for (int k0 = 0; k0 < K; k0 += 32) {
        int kk = (threadIdx.x & 3) * 8;
        int gr = bm + r;
        #pragma unroll
        for (int i = 0; i < 8; i++)
            As[r][kk + i] = (gr < M) ? A[(long long)gr * K + k0 + kk + i] : 0.f;
        for (int i = threadIdx.x; i < 32 * 40; i += 256) {
            int k = i / 40, n = i % 40;
            Bs[k][n] = B[(k0 + k) * 40 + n];
        }
        __syncthreads();
        #pragma unroll
        for (int k = 0; k < 32; k++) {
            float a = As[r][k];
            #pragma unroll
            for (int j = 0; j < 10; j++) acc[j] += a * Bs[k][cg + j * 4];
        }
        __syncthreads();
    }
    int gr = bm + r;
    if (gr < M)
        #pragma unroll
        for (int j = 0; j < 10; j++) C[gr * 40 + cg + j * 4] = acc[j];
}

// ---------------- gather SpMM 256ch: out[r] = d^2*in[r] + bias + sum w*in[col] ---
__global__ void __launch_bounds__(256) k_gspmm256(const float* __restrict__ in,
                                                  float* __restrict__ out,
                                                  const float* __restrict__ bias) {
    __shared__ int   scol[256];
    __shared__ float sw[256];
    int r = blockIdx.x;
    int ch = threadIdx.x;
    int beg = g_off[r], end = g_off[r + 1];
    float d = g_dinv[r];
    float acc = d * d * in[r * HID + ch] + bias[ch];
    for (int j0 = beg; j0 < end; j0 += 256) {
        int m = min(256, end - j0);
        if (ch < m) { scol[ch] = g_ccol[j0 + ch]; sw[ch] = g_cw[j0 + ch]; }
        __syncthreads();
        #pragma unroll 4
        for (int j = 0; j < m; j++)
            acc += sw[j] * in[scol[j] * HID + ch];
        __syncthreads();
    }
    out[r * HID + ch] = acc;
}

// ---------------- 40-channel gather SpMM: triple (features + 2 label chains) -----
__global__ void __launch_bounds__(256) k_gspmm40t(
    const float* __restrict__ in0, float* __restrict__ out0, const float* __restrict__ bias0,
    const float* __restrict__ in1, float* __restrict__ out1,
    const float* __restrict__ in2, float* __restrict__ out2) {
    int r = blockIdx.x * 8 + (threadIdx.x >> 5);
    if (r >= NN) return;
    int lane = threadIdx.x & 31;
    int beg = g_off[r], end = g_off[r + 1];
    float d = g_dinv[r];
    float dd = d * d;
    int rb = r * OC + lane;
    float a0 = dd * in0[rb], a1 = dd * in1[rb], a2 = dd * in2[rb];
    float b0 = 0.f, b1 = 0.f, b2 = 0.f;
    if (lane < 8) {
        b0 = dd * in0[rb + 32]; b1 = dd * in1[rb + 32]; b2 = dd * in2[rb + 32];
    }
    #pragma unroll 2
    for (int j = beg; j < end; j++) {
        int cb = g_ccol[j] * OC + lane;
        float w = g_cw[j];
        a0 += w * in0[cb]; a1 += w * in1[cb]; a2 += w * in2[cb];
        if (lane < 8) {
            b0 += w * in0[cb + 32]; b1 += w * in1[cb + 32]; b2 += w * in2[cb + 32];
        }
    }
    a0 += bias0[lane];
    out0[rb] = a0; out1[rb] = a1; out2[rb] = a2;
    if (lane < 8) {
        b0 += bias0[32 + lane];
        out0[rb + 32] = b0; out1[rb + 32] = b1; out2[rb + 32] = b2;
    }
}

// dual version (two label chains, no bias)
__global__ void __launch_bounds__(256) k_gspmm40d(
    const float* __restrict__ in1, float* __restrict__ out1,
    const float* __restrict__ in2, float* __restrict__ out2) {
    int r = blockIdx.x * 8 + (threadIdx.x >> 5);
    if (r >= NN) return;
    int lane = threadIdx.x & 31;
    int beg = g_off[r], end = g_off[r + 1];
    float d = g_dinv[r];
    float dd = d * d;
    int rb = r * OC + lane;
    float a1 = dd * in1[rb], a2 = dd * in2[rb];
    float b1 = 0.f, b2 = 0.f;
    if (lane < 8) { b1 = dd * in1[rb + 32]; b2 = dd * in2[rb + 32]; }
    #pragma unroll 2
    for (int j = beg; j < end; j++) {
        int cb = g_ccol[j] * OC + lane;
        float w = g_cw[j];
        a1 += w * in1[cb]; a2 += w * in2[cb];
        if (lane < 8) { b1 += w * in1[cb + 32]; b2 += w * in2[cb + 32]; }
    }
    out1[rb] = a1; out2[rb] = a2;
    if (lane < 8) { out1[rb + 32] = b1; out2[rb + 32] = b2; }
}

// ---------------- BatchNorm -------------------------------------------------------
__global__ void k_bnzero() {
    int c = threadIdx.x;
    g_bnsum[c] = 0.f;
    g_bnsq[c]  = 0.f;
}

__global__ void k_bnstats(const float* __restrict__ h) {
    int c = threadIdx.x;
    float s = 0.f, s2 = 0.f;
    for (int r = blockIdx.x; r < NN; r += gridDim.x) {
        float v = h[r * HID + c];
        s += v;
        s2 += v * v;
    }
    atomicAdd(&g_bnsum[c], s);
    atomicAdd(&g_bnsq[c], s2);
}

__global__ void k_bnfin(const float* __restrict__ gamma, const float* __restrict__ beta) {
    int c = threadIdx.x;
    float mu  = g_bnsum[c] * (1.f / NN);
    float var = g_bnsq[c] * (1.f / NN) - mu * mu;
    float sc  = gamma[c] * rsqrtf(var + 1e-5f);
    g_scale[c] = sc;
    g_shift[c] = beta[c] - mu * sc;
}

__global__ void k_bnapply(const float* __restrict__ in, float* __restrict__ out) {
    int idx = blockIdx.x * blockDim.x + threadIdx.x;
    if (idx < NN * HID) {
        int c = idx & 255;
        out[idx] = fmaxf(in[idx] * g_scale[c] + g_shift[c], 0.f);
    }
}

// ---------------- host orchestration ----------------------------------------------
extern "C" void kernel_launch(void* const* d_in, const int* in_sizes, int n_in,
                              void* d_out, int out_size) {
    const float* x    = (const float*)d_in[0];
    const int*   ei   = (const int*)d_in[1];
    const int*   row  = ei;
    const int*   col  = ei + NE;
    const float* lab0 = (const float*)d_in[2];
    const float* lab1 = (const float*)d_in[3];
    const float* ew   = (const float*)d_in[4];
    const float* W0   = (const float*)d_in[5];
    const float* b0   = (const float*)d_in[6];
    const float* W1   = (const float*)d_in[7];
    const float* b1   = (const float*)d_in[8];
    const float* W2   = (const float*)d_in[9];
    const float* b2   = (const float*)d_in[10];
    const float* g0   = (const float*)d_in[11];
    const float* be0  = (const float*)d_in[12];
    const float* g1   = (const float*)d_in[13];
    const float* be1  = (const float*)d_in[14];
    float* out = (float*)d_out;

    float *bufA, *bufB, *t40, *y0, *y1, *y2, *y3, *degp;
    int* cntp;
    cudaGetSymbolAddress((void**)&bufA, g_bufA);
    cudaGetSymbolAddress((void**)&bufB, g_bufB);
    cudaGetSymbolAddress((void**)&t40,  g_t40);
    cudaGetSymbolAddress((void**)&y0,   g_y0);
    cudaGetSymbolAddress((void**)&y1,   g_y1);
    cudaGetSymbolAddress((void**)&y2,   g_y2);
    cudaGetSymbolAddress((void**)&y3,   g_y3);
    cudaGetSymbolAddress((void**)&degp, g_deg);
    cudaGetSymbolAddress((void**)&cntp, g_cnt);

    const int T = 256;
    const int gN   = (NN + T - 1) / T;
    const int gE   = (NE + T - 1) / T;
    const int gNH  = (NN * HID + T - 1) / T;
    const int gM64 = (NN + 63) / 64;
    const int gRW  = (NN + 7) / 8;

    // normalization + CSR build
    k_fillinit<<<gN, T>>>(degp, cntp, NN);
    k_degcnt<<<gE, T>>>(row, ew);
    k_dinv<<<gN, T>>>();
    k_scan<<<1, 1024>>>();
    k_scatter<<<gE, T>>>(row, col, ew);

    // ---- layer 0
    dim3 gg(NNP / 128, HID / 64);
    k_gemm_tf32<<<gg, T>>>(x, W0, bufA, NN, HID, 512);
    k_gspmm256<<<NN, HID>>>(bufA, bufB, b0);
    k_bnzero<<<1, HID>>>();
    k_bnstats<<<256, HID>>>(bufB);
    k_bnfin<<<1, HID>>>(g0, be0);
    k_bnapply<<<gNH, T>>>(bufB, bufA);

    // ---- layer 1
    k_gemm_tf32<<<gg, T>>>(bufA, W1, bufB, NN, HID, 256);
    k_gspmm256<<<NN, HID>>>(bufB, bufA, b1);
    k_bnzero<<<1, HID>>>();
    k_bnstats<<<256, HID>>>(bufA);
    k_bnfin<<<1, HID>>>(g1, be1);
    k_bnapply<<<gNH, T>>>(bufA, bufB);

    // ---- layer 2 GEMM (into t40)
    k_gemm40<<<gM64, T>>>(bufB, W2, t40, NN, HID);

    // ---- fused 40-channel SpMMs
    float* dst1 = out + NN * OC;
    float* dst2 = out + 2 * NN * OC;
    // iter 1: features (with bias) + both label chains
    k_gspmm40t<<<gRW, T>>>(t40, out, b2, lab0, y0, lab1, y2);
    // iter 2 + 3 for label chains
    k_gspmm40d<<<gRW, T>>>(y0, y1, y2, y3);
    k_gspmm40d<<<gRW, T>>>(y1, dst1, y3, dst2);
}

// round 6
// speedup vs baseline: 2.5042x; 1.1514x over previous
#include <cuda_runtime.h>
#include <mma.h>
using namespace nvcuda;

#define NN  50000
#define NNP 50048          // 391 * 128, padded row count for unguarded GEMM stores
#define NE  800000
#define HID 256
#define OC  40

// ---------------- scratch (static device allocations) ---------------------------
__device__ float g_deg[NN];
__device__ float g_dinv[NN];
__device__ int   g_cnt[NN];
__device__ int   g_off[NN + 1];
__device__ int   g_cur[NN];
__device__ int   g_ccol[NE];
__device__ float g_cw[NE];
__device__ float g_bufA[NNP * HID];
__device__ float g_bufB[NNP * HID];
__device__ float g_t40[NN * OC];
__device__ float g_y0[NN * OC];
__device__ float g_y1[NN * OC];
__device__ float g_y2[NN * OC];
__device__ float g_y3[NN * OC];
__device__ float g_bnsum[HID];
__device__ float g_bnsq[HID];
__device__ float g_scale[HID];
__device__ float g_shift[HID];

// ---------------- normalization + CSR build --------------------------------------
__global__ void k_fillinit(float* degp, int* cntp, int n) {
    int i = blockIdx.x * blockDim.x + threadIdx.x;
    if (i < n) { degp[i] = 1.0f; cntp[i] = 0; }
}

__global__ void k_degcnt(const int* __restrict__ row, const float* __restrict__ w) {
    int e = blockIdx.x * blockDim.x + threadIdx.x;
    if (e < NE) {
        int r = row[e];
        atomicAdd(&g_deg[r], w[e]);
        atomicAdd(&g_cnt[r], 1);
    }
}

__global__ void k_dinv() {
    int i = blockIdx.x * blockDim.x + threadIdx.x;
    if (i < NN) {
        float d = g_deg[i];
        g_dinv[i] = (d > 0.f) ? rsqrtf(fmaxf(d, 1e-12f)) : 0.f;
    }
}

// single-block exclusive scan over g_cnt -> g_off, warp-shuffle based
__global__ void k_scan() {
    __shared__ int wsum[32];
    __shared__ int carry_s;
    int tid = threadIdx.x, lane = tid & 31, wid = tid >> 5;
    if (tid == 0) carry_s = 0;
    __syncthreads();
    for (int base = 0; base < NN; base += 1024) {
        int i = base + tid;
        int v = (i < NN) ? g_cnt[i] : 0;
        int x = v;
        #pragma unroll
        for (int o = 1; o < 32; o <<= 1) {
            int t = __shfl_up_sync(0xFFFFFFFFu, x, o);
            if (lane >= o) x += t;
        }
        if (lane == 31) wsum[wid] = x;
        __syncthreads();
        if (wid == 0) {
            int s = wsum[lane];
            #pragma unroll
            for (int o = 1; o < 32; o <<= 1) {
                int t = __shfl_up_sync(0xFFFFFFFFu, s, o);
                if (lane >= o) s += t;
            }
            wsum[lane] = s;
        }
        __syncthreads();
        int warpoff = (wid > 0) ? wsum[wid - 1] : 0;
        int incl = carry_s + warpoff + x;
        if (i < NN) {
            int excl = incl - v;
            g_off[i] = excl;
            g_cur[i] = excl;
        }
        __syncthreads();
        if (tid == 1023) carry_s = incl;
        __syncthreads();
    }
    if (tid == 0) g_off[NN] = carry_s;
}

__global__ void k_scatter(const int* __restrict__ row, const int* __restrict__ col,
                          const float* __restrict__ w) {
    int e = blockIdx.x * blockDim.x + threadIdx.x;
    if (e < NE) {
        int r = row[e], c = col[e];
        int p = atomicAdd(&g_cur[r], 1);
        g_ccol[p] = c;
        g_cw[p] = g_dinv[r] * w[e] * g_dinv[c];
    }
}

// ---------------- TF32 tensor-core GEMM: C[M,N] = op(A)[M,K] @ B[K,N] ------------
// block tile 128x64, 8 warps (4 m x 2 n), warp tile 32x32.
// bn != 0: A element (channel = k index) is transformed relu(a*scale[k]+shift[k]).
__global__ void __launch_bounds__(256) k_gemm_tf32(const float* __restrict__ A,
                                                   const float* __restrict__ B,
                                                   float* __restrict__ C,
                                                   int M, int N, int K, int bn) {
    __shared__ float As[128][40];   // [m][k], k chunk 32
    __shared__ float Bs[32][72];    // [k][n], n chunk 64
    int bm = blockIdx.x * 128, bnn = blockIdx.y * 64;
    int tid = threadIdx.x;
    int warp = tid >> 5;
    int wm = (warp >> 1) * 32;
    int wn = (warp & 1) * 32;

    wmma::fragment<wmma::accumulator, 16, 16, 8, float> c00, c01, c10, c11;
    wmma::fill_fragment(c00, 0.f); wmma::fill_fragment(c01, 0.f);
    wmma::fill_fragment(c10, 0.f); wmma::fill_fragment(c11, 0.f);

    for (int k0 = 0; k0 < K; k0 += 32) {
        {
            int m  = tid >> 1;
            int ks = (tid & 1) * 16;
            int gr = bm + m;
            if (gr < M) {
                const float4* p = (const float4*)&A[(long long)gr * K + k0 + ks];
                #pragma unroll
                for (int i = 0; i < 4; i++) {
                    float4 v = p[i];
                    if (bn) {
                        int c = k0 + ks + i * 4;
                        v.x = fmaxf(v.x * g_scale[c + 0] + g_shift[c + 0], 0.f);
                        v.y = fmaxf(v.y * g_scale[c + 1] + g_shift[c + 1], 0.f);
                        v.z = fmaxf(v.z * g_scale[c + 2] + g_shift[c + 2], 0.f);
                        v.w = fmaxf(v.w * g_scale[c + 3] + g_shift[c + 3], 0.f);
                    }
                    As[m][ks + i * 4 + 0] = wmma::__float_to_tf32(v.x);
                    As[m][ks + i * 4 + 1] = wmma::__float_to_tf32(v.y);
                    As[m][ks + i * 4 + 2] = wmma::__float_to_tf32(v.z);
                    As[m][ks + i * 4 + 3] = wmma::__float_to_tf32(v.w);
                }
            } else {
                #pragma unroll
                for (int i = 0; i < 16; i++) As[m][ks + i] = 0.f;
            }
        }
        {
            int k  = tid >> 3;
            int n8 = (tid & 7) * 8;
            const float4* p = (const float4*)&B[(long long)(k0 + k) * N + bnn + n8];
            #pragma unroll
            for (int i = 0; i < 2; i++) {
                float4 v = p[i];
                Bs[k][n8 + i * 4 + 0] = wmma::__float_to_tf32(v.x);
                Bs[k][n8 + i * 4 + 1] = wmma::__float_to_tf32(v.y);
                Bs[k][n8 + i * 4 + 2] = wmma::__float_to_tf32(v.z);
                Bs[k][n8 + i * 4 + 3] = wmma::__float_to_tf32(v.w);
            }
        }
        __syncthreads();
        #pragma unroll
        for (int kk = 0; kk < 32; kk += 8) {
            wmma::fragment<wmma::matrix_a, 16, 16, 8, wmma::precision::tf32, wmma::row_major> a0, a1;
            wmma::fragment<wmma::matrix_b, 16, 16, 8, wmma::precision::tf32, wmma::row_major> b0, b1;
            wmma::load_matrix_sync(a0, &As[wm +  0][kk], 40);
            wmma::load_matrix_sync(a1, &As[wm + 16][kk], 40);
            wmma::load_matrix_sync(b0, &Bs[kk][wn +  0], 72);
            wmma::load_matrix_sync(b1, &Bs[kk][wn + 16], 72);
            wmma::mma_sync(c00, a0, b0, c00);
            wmma::mma_sync(c01, a0, b1, c01);
            wmma::mma_sync(c10, a1, b0, c10);
            wmma::mma_sync(c11, a1, b1, c11);
        }
        __syncthreads();
    }
    float* cp = &C[(long long)(bm + wm) * N + bnn + wn];
    wmma::store_matrix_sync(cp,               c00, N, wmma::mem_row_major);
    wmma::store_matrix_sync(cp + 16,          c01, N, wmma::mem_row_major);
    wmma::store_matrix_sync(cp + 16 * N,      c10, N, wmma::mem_row_major);
    wmma::store_matrix_sync(cp + 16 * N + 16, c11, N, wmma::mem_row_major);
}

// ---------------- GEMM: C[M,40] = relu(bn(A))[M,K] @ B[K,40] (SIMT) --------------
__global__ void k_gemm40(const float* __restrict__ A, const float* __restrict__ B,
                         float* __restrict__ C, int M, int K) {
    __shared__ float As[64][33];
    __shared__ float Bs[32][40];
    int bm = blockIdx.x * 64;
    int r  = threadIdx.x >> 2;
    int cg = threadIdx.x & 3;
    float acc[10] = {};
    for (int k0 = 0; k0 < K; k0 += 32) {
        int kk = (threadIdx.x & 3) * 8;
        int gr = bm + r;
        #pragma unroll
        for (int i = 0; i < 8; i++) {
            int c = k0 + kk + i;
            float v = (gr < M) ? A[(long long)gr * K + c] : 0.f;
            As[r][kk + i] = fmaxf(v * g_scale[c] + g_shift[c], 0.f);
        }
        for (int i = threadIdx.x; i < 32 * 40; i += 256) {
            int k = i / 40, n = i % 40;
            Bs[k][n] = B[(k0 + k) * 40 + n];
        }
        __syncthreads();
        #pragma unroll
        for (int k = 0; k < 32; k++) {
            float a = As[r][k];
            #pragma unroll
            for (int j = 0; j < 10; j++) acc[j] += a * Bs[k][cg + j * 4];
        }
        __syncthreads();
    }
    int gr = bm + r;
    if (gr < M)
        #pragma unroll
        for (int j = 0; j < 10; j++) C[gr * 40 + cg + j * 4] = acc[j];
}

// ---------------- gather SpMM 256ch: out[r] = d^2*in[r] + bias + sum w*in[col] ---
__global__ void __launch_bounds__(256) k_gspmm256(const float* __restrict__ in,
                                                  float* __restrict__ out,
                                                  const float* __restrict__ bias) {
    __shared__ int   scol[256];
    __shared__ float sw[256];
    int r = blockIdx.x;
    int ch = threadIdx.x;
    int beg = g_off[r], end = g_off[r + 1];
    float d = g_dinv[r];
    float acc = d * d * in[r * HID + ch] + bias[ch];
    for (int j0 = beg; j0 < end; j0 += 256) {
        int m = min(256, end - j0);
        if (ch < m) { scol[ch] = g_ccol[j0 + ch]; sw[ch] = g_cw[j0 + ch]; }
        __syncthreads();
        #pragma unroll 4
        for (int j = 0; j < m; j++)
            acc += sw[j] * in[scol[j] * HID + ch];
        __syncthreads();
    }
    out[r * HID + ch] = acc;
}

// ---------------- 40-channel gather SpMM: triple (features + 2 label chains) -----
__global__ void __launch_bounds__(256) k_gspmm40t(
    const float* __restrict__ in0, float* __restrict__ out0, const float* __restrict__ bias0,
    const float* __restrict__ in1, float* __restrict__ out1,
    const float* __restrict__ in2, float* __restrict__ out2) {
    int r = blockIdx.x * 8 + (threadIdx.x >> 5);
    if (r >= NN) return;
    int lane = threadIdx.x & 31;
    int beg = g_off[r], end = g_off[r + 1];
    float d = g_dinv[r];
    float dd = d * d;
    int rb = r * OC + lane;
    float a0 = dd * in0[rb], a1 = dd * in1[rb], a2 = dd * in2[rb];
    float b0 = 0.f, b1 = 0.f, b2 = 0.f;
    if (lane < 8) {
        b0 = dd * in0[rb + 32]; b1 = dd * in1[rb + 32]; b2 = dd * in2[rb + 32];
    }
    #pragma unroll 2
    for (int j = beg; j < end; j++) {
        int cb = g_ccol[j] * OC + lane;
        float w = g_cw[j];
        a0 += w * in0[cb]; a1 += w * in1[cb]; a2 += w * in2[cb];
        if (lane < 8) {
            b0 += w * in0[cb + 32]; b1 += w * in1[cb + 32]; b2 += w * in2[cb + 32];
        }
    }
    a0 += bias0[lane];
    out0[rb] = a0; out1[rb] = a1; out2[rb] = a2;
    if (lane < 8) {
        b0 += bias0[32 + lane];
        out0[rb + 32] = b0; out1[rb + 32] = b1; out2[rb + 32] = b2;
    }
}

// dual version (two label chains, no bias)
__global__ void __launch_bounds__(256) k_gspmm40d(
    const float* __restrict__ in1, float* __restrict__ out1,
    const float* __restrict__ in2, float* __restrict__ out2) {
    int r = blockIdx.x * 8 + (threadIdx.x >> 5);
    if (r >= NN) return;
    int lane = threadIdx.x & 31;
    int beg = g_off[r], end = g_off[r + 1];
    float d = g_dinv[r];
    float dd = d * d;
    int rb = r * OC + lane;
    float a1 = dd * in1[rb], a2 = dd * in2[rb];
    float b1 = 0.f, b2 = 0.f;
    if (lane < 8) { b1 = dd * in1[rb + 32]; b2 = dd * in2[rb + 32]; }
    #pragma unroll 2
    for (int j = beg; j < end; j++) {
        int cb = g_ccol[j] * OC + lane;
        float w = g_cw[j];
        a1 += w * in1[cb]; a2 += w * in2[cb];
        if (lane < 8) { b1 += w * in1[cb + 32]; b2 += w * in2[cb + 32]; }
    }
    out1[rb] = a1; out2[rb] = a2;
    if (lane < 8) { out1[rb + 32] = b1; out2[rb + 32] = b2; }
}

// ---------------- BatchNorm stats -------------------------------------------------
__global__ void k_bnzero() {
    int c = threadIdx.x;
    g_bnsum[c] = 0.f;
    g_bnsq[c]  = 0.f;
}

__global__ void k_bnstats(const float* __restrict__ h) {
    int c = threadIdx.x;
    float s = 0.f, s2 = 0.f;
    for (int r = blockIdx.x; r < NN; r += gridDim.x) {
        float v = h[r * HID + c];
        s += v;
        s2 += v * v;
    }
    atomicAdd(&g_bnsum[c], s);
    atomicAdd(&g_bnsq[c], s2);
}

__global__ void k_bnfin(const float* __restrict__ gamma, const float* __restrict__ beta) {
    int c = threadIdx.x;
    float mu  = g_bnsum[c] * (1.f / NN);
    float var = g_bnsq[c] * (1.f / NN) - mu * mu;
    float sc  = gamma[c] * rsqrtf(var + 1e-5f);
    g_scale[c] = sc;
    g_shift[c] = beta[c] - mu * sc;
}

// ---------------- host orchestration ----------------------------------------------
extern "C" void kernel_launch(void* const* d_in, const int* in_sizes, int n_in,
                              void* d_out, int out_size) {
    const float* x    = (const float*)d_in[0];
    const int*   ei   = (const int*)d_in[1];
    const int*   row  = ei;
    const int*   col  = ei + NE;
    const float* lab0 = (const float*)d_in[2];
    const float* lab1 = (const float*)d_in[3];
    const float* ew   = (const float*)d_in[4];
    const float* W0   = (const float*)d_in[5];
    const float* b0   = (const float*)d_in[6];
    const float* W1   = (const float*)d_in[7];
    const float* b1   = (const float*)d_in[8];
    const float* W2   = (const float*)d_in[9];
    const float* b2   = (const float*)d_in[10];
    const float* g0   = (const float*)d_in[11];
    const float* be0  = (const float*)d_in[12];
    const float* g1   = (const float*)d_in[13];
    const float* be1  = (const float*)d_in[14];
    float* out = (float*)d_out;

    float *bufA, *bufB, *t40, *y0, *y1, *y2, *y3, *degp;
    int* cntp;
    cudaGetSymbolAddress((void**)&bufA, g_bufA);
    cudaGetSymbolAddress((void**)&bufB, g_bufB);
    cudaGetSymbolAddress((void**)&t40,  g_t40);
    cudaGetSymbolAddress((void**)&y0,   g_y0);
    cudaGetSymbolAddress((void**)&y1,   g_y1);
    cudaGetSymbolAddress((void**)&y2,   g_y2);
    cudaGetSymbolAddress((void**)&y3,   g_y3);
    cudaGetSymbolAddress((void**)&degp, g_deg);
    cudaGetSymbolAddress((void**)&cntp, g_cnt);

    const int T = 256;
    const int gN   = (NN + T - 1) / T;
    const int gE   = (NE + T - 1) / T;
    const int gM64 = (NN + 63) / 64;
    const int gRW  = (NN + 7) / 8;

    // normalization + CSR build
    k_fillinit<<<gN, T>>>(degp, cntp, NN);
    k_degcnt<<<gE, T>>>(row, ew);
    k_dinv<<<gN, T>>>();
    k_scan<<<1, 1024>>>();
    k_scatter<<<gE, T>>>(row, col, ew);

    // ---- layer 0: gemm -> spmm -> BN stats (apply fused into next gemm)
    dim3 gg(NNP / 128, HID / 64);
    k_gemm_tf32<<<gg, T>>>(x, W0, bufA, NN, HID, 512, 0);
    k_gspmm256<<<NN, HID>>>(bufA, bufB, b0);
    k_bnzero<<<1, HID>>>();
    k_bnstats<<<512, HID>>>(bufB);
    k_bnfin<<<1, HID>>>(g0, be0);

    // ---- layer 1: gemm (BN0+ReLU fused in A-load) -> spmm -> BN stats
    k_gemm_tf32<<<gg, T>>>(bufB, W1, bufA, NN, HID, 256, 1);
    k_gspmm256<<<NN, HID>>>(bufA, bufB, b1);
    k_bnzero<<<1, HID>>>();
    k_bnstats<<<512, HID>>>(bufB);
    k_bnfin<<<1, HID>>>(g1, be1);

    // ---- layer 2 GEMM (BN1+ReLU fused in A-load) into t40
    k_gemm40<<<gM64, T>>>(bufB, W2, t40, NN, HID);

    // ---- fused 40-channel SpMMs
    float* dst1 = out + NN * OC;
    float* dst2 = out + 2 * NN * OC;
    k_gspmm40t<<<gRW, T>>>(t40, out, b2, lab0, y0, lab1, y2);
    k_gspmm40d<<<gRW, T>>>(y0, y1, y2, y3);
    k_gspmm40d<<<gRW, T>>>(y1, dst1, y3, dst2);
}